// round 4
// baseline (speedup 1.0000x reference)
#include <cuda_runtime.h>
#include <cuda_bf16.h>
#include <math.h>
#include <float.h>

// Problem constants (fixed by setup_inputs)
#define BQ    1024
#define DIM   1024
#define CDIM  128
#define NKEYS 100000
#define KNN   5
#define EPSW  1e-6f
#define CAP   49152
#define NB    2048
#define TAUB  128      // tau stage-1 blocks

// ---------------- scratch (device globals; no allocations allowed) ---------
__device__ float g_h1[BQ * (DIM / 2)];
__device__ float g_h2[BQ * (DIM / 4)];
__device__ float g_cq[BQ * CDIM];
__device__ float g_qn[BQ];
__device__ int   g_Qmax_bits;
__device__ float g_kn[NKEYS];
__device__ float g_tau;
__device__ float g_invw;
__device__ float g_w;
__device__ int   g_hist[NB];
__device__ int   g_cursor[NB];
__device__ int   g_cand_count;
__device__ int   g_scand[CAP];
__device__ float g_skn[CAP];
__device__ float g_sblo[CAP];
__device__ float g_weighted[BQ * CDIM];
__device__ float g_g1[BQ * (DIM / 4)];
__device__ float g_g2[BQ * (DIM / 2)];
__device__ float g_taupart[TAUB * KNN];

// ---------------- init ------------------------------------------------------
__global__ void init_kernel() {
    int t = blockIdx.x * blockDim.x + threadIdx.x;
    if (t == 0) { g_Qmax_bits = 0; g_cand_count = 0; }
    if (t < NB) g_hist[t] = 0;
}

// ============================================================================
// Tensor-core GEMM: C = act(A[MxK] * B[KxN] + bias), fp32 in/out.
// bf16 hi/lo split (AhBh + AhBl + AlBh), fp32 accumulate via
// mma.sync.m16n8k16. Block tile 128x128, BK=32, 8 warps (warp tile 32x64).
// Requires: M%128==0, N%128==0, K%32==0 (true for all six layers here).
// ============================================================================
__device__ __forceinline__ void mma_bf16(float c[4], const unsigned a[4],
                                         const unsigned b[2]) {
    asm volatile(
        "mma.sync.aligned.m16n8k16.row.col.f32.bf16.bf16.f32 "
        "{%0,%1,%2,%3}, {%4,%5,%6,%7}, {%8,%9}, {%0,%1,%2,%3};"
        : "+f"(c[0]), "+f"(c[1]), "+f"(c[2]), "+f"(c[3])
        : "r"(a[0]), "r"(a[1]), "r"(a[2]), "r"(a[3]), "r"(b[0]), "r"(b[1]));
}

__device__ __forceinline__ void ldmA(unsigned a[4], unsigned addr) {
    asm volatile("ldmatrix.sync.aligned.m8n8.x4.shared.b16 {%0,%1,%2,%3}, [%4];"
                 : "=r"(a[0]), "=r"(a[1]), "=r"(a[2]), "=r"(a[3]) : "r"(addr));
}

__device__ __forceinline__ void ldmB(unsigned b[2], unsigned addr) {
    asm volatile("ldmatrix.sync.aligned.m8n8.x2.trans.shared.b16 {%0,%1}, [%2];"
                 : "=r"(b[0]), "=r"(b[1]) : "r"(addr));
}

#define AS_STRIDE 40    // bf16 elems per A smem row (32 + pad)
#define BS_STRIDE 136   // bf16 elems per B smem row (128 + pad)

template <int RELU>
__global__ __launch_bounds__(256)
void mma_gemm_bias(const float* __restrict__ A,
                   const float* __restrict__ Bm,
                   const float* __restrict__ bias,
                   float* __restrict__ Cm,
                   int M, int N, int K) {
    __shared__ __align__(16) __nv_bfloat16 As_h[128 * AS_STRIDE];
    __shared__ __align__(16) __nv_bfloat16 As_l[128 * AS_STRIDE];
    __shared__ __align__(16) __nv_bfloat16 Bs_h[32 * BS_STRIDE];
    __shared__ __align__(16) __nv_bfloat16 Bs_l[32 * BS_STRIDE];

    const int tid  = threadIdx.x;
    const int lane = tid & 31;
    const int wid  = tid >> 5;
    const int wm   = wid & 3;        // 4 warps along M (32 rows each)
    const int wn   = wid >> 2;       // 2 warps along N (64 cols each)
    const int bm   = blockIdx.y * 128;
    const int bn   = blockIdx.x * 128;

    float acc[2][8][4];
#pragma unroll
    for (int mt = 0; mt < 2; mt++)
#pragma unroll
        for (int nt = 0; nt < 8; nt++)
#pragma unroll
            for (int i = 0; i < 4; i++) acc[mt][nt][i] = 0.f;

    // gmem staging: A 4x float4 per thread, B 4x float4 per thread
    const int arow = tid >> 3;          // 0..31 (+p*32)
    const int acol = (tid & 7) * 4;     // 0..28
    const int bkr  = tid >> 5;          // 0..7  (+p*8)
    const int bcol = lane * 4;          // 0..124

    float4 va[4], vb[4];
    const int ntk = K >> 5;
#pragma unroll
    for (int p = 0; p < 4; p++) {
        va[p] = *reinterpret_cast<const float4*>(
            &A[(size_t)(bm + arow + p * 32) * K + acol]);
        vb[p] = *reinterpret_cast<const float4*>(
            &Bm[(size_t)(bkr + p * 8) * N + bn + bcol]);
    }

    const unsigned ash = (unsigned)__cvta_generic_to_shared(As_h);
    const unsigned asl = (unsigned)__cvta_generic_to_shared(As_l);
    const unsigned bsh = (unsigned)__cvta_generic_to_shared(Bs_h);
    const unsigned bsl = (unsigned)__cvta_generic_to_shared(Bs_l);

    // ldmatrix address components
    const int a_r  = (lane & 7) + ((lane >> 3) & 1) * 8;  // row within 16
    const int a_k8 = (lane >> 4) * 8;                     // k half select
    const int b_r  = lane & 15;                           // k row within 16

    for (int t = 0; t < ntk; t++) {
        __syncthreads();   // previous tile's mma done; smem reusable
        // split + store staged tiles
#pragma unroll
        for (int p = 0; p < 4; p++) {
            float xa[4] = {va[p].x, va[p].y, va[p].z, va[p].w};
            unsigned short h[4], l[4];
#pragma unroll
            for (int i = 0; i < 4; i++) {
                __nv_bfloat16 hb = __float2bfloat16(xa[i]);
                __nv_bfloat16 lb = __float2bfloat16(xa[i] - __bfloat162float(hb));
                h[i] = __bfloat16_as_ushort(hb);
                l[i] = __bfloat16_as_ushort(lb);
            }
            int off = (arow + p * 32) * AS_STRIDE + acol;
            *reinterpret_cast<unsigned*>(&As_h[off])     = (unsigned)h[0] | ((unsigned)h[1] << 16);
            *reinterpret_cast<unsigned*>(&As_h[off + 2]) = (unsigned)h[2] | ((unsigned)h[3] << 16);
            *reinterpret_cast<unsigned*>(&As_l[off])     = (unsigned)l[0] | ((unsigned)l[1] << 16);
            *reinterpret_cast<unsigned*>(&As_l[off + 2]) = (unsigned)l[2] | ((unsigned)l[3] << 16);

            float xb[4] = {vb[p].x, vb[p].y, vb[p].z, vb[p].w};
#pragma unroll
            for (int i = 0; i < 4; i++) {
                __nv_bfloat16 hb = __float2bfloat16(xb[i]);
                __nv_bfloat16 lb = __float2bfloat16(xb[i] - __bfloat162float(hb));
                h[i] = __bfloat16_as_ushort(hb);
                l[i] = __bfloat16_as_ushort(lb);
            }
            off = (bkr + p * 8) * BS_STRIDE + bcol;
            *reinterpret_cast<unsigned*>(&Bs_h[off])     = (unsigned)h[0] | ((unsigned)h[1] << 16);
            *reinterpret_cast<unsigned*>(&Bs_h[off + 2]) = (unsigned)h[2] | ((unsigned)h[3] << 16);
            *reinterpret_cast<unsigned*>(&Bs_l[off])     = (unsigned)l[0] | ((unsigned)l[1] << 16);
            *reinterpret_cast<unsigned*>(&Bs_l[off + 2]) = (unsigned)l[2] | ((unsigned)l[3] << 16);
        }
        __syncthreads();   // tile visible

        if (t + 1 < ntk) {  // prefetch next tile (overlaps with mma below)
            const int kadv = (t + 1) * 32;
#pragma unroll
            for (int p = 0; p < 4; p++) {
                va[p] = *reinterpret_cast<const float4*>(
                    &A[(size_t)(bm + arow + p * 32) * K + kadv + acol]);
                vb[p] = *reinterpret_cast<const float4*>(
                    &Bm[(size_t)(kadv + bkr + p * 8) * N + bn + bcol]);
            }
        }

#pragma unroll
        for (int kk = 0; kk < 32; kk += 16) {
            unsigned ah[2][4], al_[2][4];
#pragma unroll
            for (int mt = 0; mt < 2; mt++) {
                unsigned rowoff =
                    ((wm * 32 + mt * 16 + a_r) * AS_STRIDE + kk + a_k8) * 2;
                ldmA(ah[mt],  ash + rowoff);
                ldmA(al_[mt], asl + rowoff);
            }
#pragma unroll
            for (int nt = 0; nt < 8; nt++) {
                unsigned bh[2], bl_[2];
                unsigned boff =
                    ((kk + b_r) * BS_STRIDE + wn * 64 + nt * 8) * 2;
                ldmB(bh,  bsh + boff);
                ldmB(bl_, bsl + boff);
#pragma unroll
                for (int mt = 0; mt < 2; mt++) {
                    mma_bf16(acc[mt][nt], ah[mt],  bh);
                    mma_bf16(acc[mt][nt], ah[mt],  bl_);
                    mma_bf16(acc[mt][nt], al_[mt], bh);
                }
            }
        }
    }

    // epilogue: bias + optional ReLU
    const int g  = lane >> 2;
    const int tq = lane & 3;
#pragma unroll
    for (int mt = 0; mt < 2; mt++) {
#pragma unroll
        for (int nt = 0; nt < 8; nt++) {
            int row = bm + wm * 32 + mt * 16 + g;
            int col = bn + wn * 64 + nt * 8 + tq * 2;
            float bz0 = bias[col], bz1 = bias[col + 1];
            float v0 = acc[mt][nt][0] + bz0;
            float v1 = acc[mt][nt][1] + bz1;
            float v2 = acc[mt][nt][2] + bz0;
            float v3 = acc[mt][nt][3] + bz1;
            if (RELU) {
                v0 = fmaxf(v0, 0.f); v1 = fmaxf(v1, 0.f);
                v2 = fmaxf(v2, 0.f); v3 = fmaxf(v3, 0.f);
            }
            float2 o0 = {v0, v1}, o1 = {v2, v3};
            *reinterpret_cast<float2*>(&Cm[(size_t)row * N + col]) = o0;
            *reinterpret_cast<float2*>(&Cm[(size_t)(row + 8) * N + col]) = o1;
        }
    }
}

// ---------------- row squared-norms (rows of width 128) --------------------
__global__ void rownorm_kernel(const float* __restrict__ X,
                               float* __restrict__ out, int rows, int do_qmax) {
    int gw = (int)((blockIdx.x * (size_t)blockDim.x + threadIdx.x) >> 5);
    int lane = threadIdx.x & 31;
    if (gw >= rows) return;
    float4 v = reinterpret_cast<const float4*>(X + (size_t)gw * 128)[lane];
    float s = v.x * v.x + v.y * v.y + v.z * v.z + v.w * v.w;
#pragma unroll
    for (int o = 16; o; o >>= 1) s += __shfl_xor_sync(0xffffffffu, s, o);
    if (lane == 0) {
        out[gw] = s;
        if (do_qmax) atomicMax(&g_Qmax_bits, __float_as_int(s));
    }
}

// ---------------- tau: parallel 5-smallest of upper bounds -----------------
__global__ void tau_part_kernel() {
    __shared__ float sv[256 * KNN];
    const int tid = threadIdx.x;
    const float Q = sqrtf(__int_as_float(g_Qmax_bits));
    float t5[KNN] = {3.4e38f, 3.4e38f, 3.4e38f, 3.4e38f, 3.4e38f};
    for (int n = blockIdx.x * blockDim.x + tid; n < NKEYS;
         n += gridDim.x * blockDim.x) {
        float kn = g_kn[n];
        float u = kn + 2.f * Q * sqrtf(kn) + 1e-3f;
        if (u < t5[KNN - 1]) {
            int p = KNN - 1;
            while (p > 0 && t5[p - 1] > u) { t5[p] = t5[p - 1]; p--; }
            t5[p] = u;
        }
    }
#pragma unroll
    for (int i = 0; i < KNN; i++) sv[tid * KNN + i] = t5[i];
    __syncthreads();
    for (int stride = 128; stride >= 1; stride >>= 1) {
        if (tid < stride) {
            float a[KNN], b[KNN], m[KNN];
#pragma unroll
            for (int i = 0; i < KNN; i++) {
                a[i] = sv[tid * KNN + i];
                b[i] = sv[(tid + stride) * KNN + i];
            }
            int ia = 0, ib = 0;
#pragma unroll
            for (int i = 0; i < KNN; i++) m[i] = (a[ia] <= b[ib]) ? a[ia++] : b[ib++];
#pragma unroll
            for (int i = 0; i < KNN; i++) sv[tid * KNN + i] = m[i];
        }
        __syncthreads();
    }
    if (tid < KNN) g_taupart[blockIdx.x * KNN + tid] = sv[tid];
}

__global__ void tau_final_kernel() {
    __shared__ float sv[TAUB * KNN];
    const int tid = threadIdx.x;   // TAUB threads
#pragma unroll
    for (int i = 0; i < KNN; i++) sv[tid * KNN + i] = g_taupart[tid * KNN + i];
    __syncthreads();
    for (int stride = TAUB / 2; stride >= 1; stride >>= 1) {
        if (tid < stride) {
            float a[KNN], b[KNN], m[KNN];
#pragma unroll
            for (int i = 0; i < KNN; i++) {
                a[i] = sv[tid * KNN + i];
                b[i] = sv[(tid + stride) * KNN + i];
            }
            int ia = 0, ib = 0;
#pragma unroll
            for (int i = 0; i < KNN; i++) m[i] = (a[ia] <= b[ib]) ? a[ia++] : b[ib++];
#pragma unroll
            for (int i = 0; i < KNN; i++) sv[tid * KNN + i] = m[i];
        }
        __syncthreads();
    }
    if (tid == 0) {
        const float Q = sqrtf(__int_as_float(g_Qmax_bits));
        float tau = sv[KNN - 1] + 1e-2f;
        g_tau = tau;
        float r = Q + sqrtf(Q * Q + tau);
        float hi = r * r * 1.02f + 1.f;
        g_invw = (float)NB / hi;
        g_w = hi / (float)NB;
    }
}

// ---------------- pass 1: histogram candidates by kn bucket -----------------
__global__ void cand_hist_kernel() {
    int n = blockIdx.x * blockDim.x + threadIdx.x;
    if (n >= NKEYS) return;
    float Q = sqrtf(__int_as_float(g_Qmax_bits));
    float kn = g_kn[n];
    float l = kn - 2.f * Q * sqrtf(kn) - 1e-3f;
    if (l <= g_tau) {
        int b = min(NB - 1, (int)(kn * g_invw));
        atomicAdd(&g_hist[b], 1);
    }
}

// ---------------- exclusive scan over NB buckets (one block) ----------------
__global__ void scan_kernel() {
    __shared__ int s[NB];
    __shared__ int tmp[NB];
    const int tid = threadIdx.x;   // 1024
    for (int i = tid; i < NB; i += 1024) s[i] = g_hist[i];
    __syncthreads();
    for (int off = 1; off < NB; off <<= 1) {
        for (int i = tid; i < NB; i += 1024)
            tmp[i] = s[i] + (i >= off ? s[i - off] : 0);
        __syncthreads();
        for (int i = tid; i < NB; i += 1024) s[i] = tmp[i];
        __syncthreads();
    }
    for (int i = tid; i < NB; i += 1024)
        g_cursor[i] = (i == 0) ? 0 : s[i - 1];
    if (tid == 0) g_cand_count = s[NB - 1];
}

// ---------------- pass 2: scatter into bucket-sorted arrays -----------------
__global__ void scatter_kernel() {
    int n = blockIdx.x * blockDim.x + threadIdx.x;
    if (n >= NKEYS) return;
    float Q = sqrtf(__int_as_float(g_Qmax_bits));
    float kn = g_kn[n];
    float l = kn - 2.f * Q * sqrtf(kn) - 1e-3f;
    if (l <= g_tau) {
        int b = min(NB - 1, (int)(kn * g_invw));
        int pos = atomicAdd(&g_cursor[b], 1);
        if (pos < CAP) {
            g_scand[pos] = n;
            g_skn[pos]   = kn;
            g_sblo[pos]  = (float)b * g_w;
        }
    }
}

// ---------------- exact rescore + top-5 + weighted gather ------------------
__global__ __launch_bounds__(128, 8)
void rescore_kernel(const float* __restrict__ keys,
                    const float* __restrict__ values,
                    float* __restrict__ conf_out) {
    const int b = blockIdx.x;
    const int tid = threadIdx.x;
    __shared__ float sq[CDIM];
    __shared__ float dv[128];
    __shared__ int   di[128];
    __shared__ float rd[KNN];
    __shared__ int   ri[KNN];
    __shared__ float rv[128];
    __shared__ int   rvi[128];
    __shared__ int   rvj[128];
    __shared__ float sw[KNN];
    __shared__ int   s_stop;

    sq[tid] = g_cq[(size_t)b * CDIM + tid];
    if (tid < KNN) { rd[tid] = 3.4e38f; ri[tid] = 0x7fffffff; }
    if (tid == 0) s_stop = 0;
    int count = g_cand_count;
    if (count > CAP) count = CAP;
    const float qn = g_qn[b];
    const float qb = sqrtf(qn);
    __syncthreads();

    for (int c0 = 0; c0 < count; c0 += 128) {
        if (tid == 0 && c0 > 0) {
            float blo = g_sblo[c0];
            float lb = qn + blo - 2.f * qb * sqrtf(blo) - 1e-3f;
            if (lb > rd[KNN - 1]) s_stop = 1;
        }
        __syncthreads();
        if (s_stop) break;

        int len = min(128, count - c0);
        int j = c0 + tid;
        if (tid < len) {
            int n = g_scand[j];
            const float4* kr = reinterpret_cast<const float4*>(keys + (size_t)n * CDIM);
            const float4* sq4 = reinterpret_cast<const float4*>(sq);
            float a0 = 0.f, a1 = 0.f, a2 = 0.f, a3 = 0.f;
#pragma unroll
            for (int d = 0; d < CDIM / 4; d++) {
                float4 kv = __ldg(&kr[d]);
                float4 qv = sq4[d];
                a0 = fmaf(qv.x, kv.x, a0);
                a1 = fmaf(qv.y, kv.y, a1);
                a2 = fmaf(qv.z, kv.z, a2);
                a3 = fmaf(qv.w, kv.w, a3);
            }
            float dot = (a0 + a1) + (a2 + a3);
            dv[tid] = qn + g_skn[j] - 2.f * dot;
            di[tid] = n;
        } else {
            dv[tid] = 3.4e38f;
            di[tid] = 0x7fffffff;
        }
        __syncthreads();

        for (int r = 0; r < KNN; r++) {
            rv[tid] = dv[tid]; rvi[tid] = di[tid]; rvj[tid] = tid;
            __syncthreads();
#pragma unroll
            for (int s = 64; s >= 1; s >>= 1) {
                if (tid < s) {
                    if (rv[tid + s] < rv[tid] ||
                        (rv[tid + s] == rv[tid] && rvi[tid + s] < rvi[tid])) {
                        rv[tid] = rv[tid + s];
                        rvi[tid] = rvi[tid + s];
                        rvj[tid] = rvj[tid + s];
                    }
                }
                __syncthreads();
            }
            if (tid == 0) {
                float v = rv[0]; int n = rvi[0];
                if (v < rd[KNN - 1] || (v == rd[KNN - 1] && n < ri[KNN - 1])) {
                    int p = KNN - 1;
                    while (p > 0 && (rd[p - 1] > v ||
                                     (rd[p - 1] == v && ri[p - 1] > n))) {
                        rd[p] = rd[p - 1]; ri[p] = ri[p - 1]; p--;
                    }
                    rd[p] = v; ri[p] = n;
                }
                dv[rvj[0]] = 3.4e38f;
            }
            __syncthreads();
        }
    }

    if (tid == 0) {
        float w[KNN], ws = 0.f;
#pragma unroll
        for (int j2 = 0; j2 < KNN; j2++) { w[j2] = 1.f / (rd[j2] + EPSW); ws += w[j2]; }
#pragma unroll
        for (int j2 = 0; j2 < KNN; j2++) sw[j2] = w[j2] / ws;
        conf_out[b] = 1.f / (rd[0] + EPSW);
    }
    __syncthreads();

    float acc = 0.f;
#pragma unroll
    for (int j2 = 0; j2 < KNN; j2++)
        acc += sw[j2] * values[(size_t)ri[j2] * CDIM + tid];
    g_weighted[(size_t)b * CDIM + tid] = acc;
}

// ---------------- launch ----------------------------------------------------
extern "C" void kernel_launch(void* const* d_in, const int* in_sizes, int n_in,
                              void* d_out, int out_size) {
    const float* query = (const float*)d_in[0];
    const float* W1    = (const float*)d_in[1];
    const float* b1    = (const float*)d_in[2];
    const float* W2    = (const float*)d_in[3];
    const float* b2    = (const float*)d_in[4];
    const float* W3    = (const float*)d_in[5];
    const float* b3    = (const float*)d_in[6];
    const float* keys  = (const float*)d_in[7];
    const float* values= (const float*)d_in[8];
    const float* D1w   = (const float*)d_in[9];
    const float* D1b   = (const float*)d_in[10];
    const float* D2w   = (const float*)d_in[11];
    const float* D2b   = (const float*)d_in[12];
    const float* D3w   = (const float*)d_in[13];
    const float* D3b   = (const float*)d_in[14];

    float* out  = (float*)d_out;
    float* conf = out + (size_t)BQ * DIM;

    float *p_h1, *p_h2, *p_cq, *p_qn, *p_kn, *p_w, *p_g1, *p_g2;
    cudaGetSymbolAddress((void**)&p_h1, g_h1);
    cudaGetSymbolAddress((void**)&p_h2, g_h2);
    cudaGetSymbolAddress((void**)&p_cq, g_cq);
    cudaGetSymbolAddress((void**)&p_qn, g_qn);
    cudaGetSymbolAddress((void**)&p_kn, g_kn);
    cudaGetSymbolAddress((void**)&p_w,  g_weighted);
    cudaGetSymbolAddress((void**)&p_g1, g_g1);
    cudaGetSymbolAddress((void**)&p_g2, g_g2);

    init_kernel<<<NB / 256, 256>>>();

    // Key norms (independent of encode chain)
    rownorm_kernel<<<(NKEYS * 32 + 255) / 256, 256>>>(keys, p_kn, NKEYS, 0);

    // Encode MLP: 1024 -> 512 -> 256 -> 128  (tensor cores, bf16 hi/lo split)
    mma_gemm_bias<1><<<dim3(512 / 128, BQ / 128), 256>>>(query, W1, b1, p_h1, BQ, 512, 1024);
    mma_gemm_bias<1><<<dim3(256 / 128, BQ / 128), 256>>>(p_h1, W2, b2, p_h2, BQ, 256, 512);
    mma_gemm_bias<0><<<dim3(128 / 128, BQ / 128), 256>>>(p_h2, W3, b3, p_cq, BQ, 128, 256);

    // Query norms + Qmax
    rownorm_kernel<<<(BQ * 32 + 255) / 256, 256>>>(p_cq, p_qn, BQ, 1);

    // Candidate filter -> bucket-sorted candidate list
    tau_part_kernel<<<TAUB, 256>>>();
    tau_final_kernel<<<1, TAUB>>>();
    cand_hist_kernel<<<(NKEYS + 255) / 256, 256>>>();
    scan_kernel<<<1, 1024>>>();
    scatter_kernel<<<(NKEYS + 255) / 256, 256>>>();

    // Exact rescore (fp32) with safe early exit, top-5, weights, gather
    rescore_kernel<<<BQ, 128>>>(keys, values, conf);

    // Decode MLP: 128 -> 256 -> 512 -> 1024
    mma_gemm_bias<1><<<dim3(256 / 128, BQ / 128), 256>>>(p_w,  D1w, D1b, p_g1, BQ, 256, 128);
    mma_gemm_bias<1><<<dim3(512 / 128, BQ / 128), 256>>>(p_g1, D2w, D2b, p_g2, BQ, 512, 256);
    mma_gemm_bias<0><<<dim3(1024 / 128, BQ / 128), 256>>>(p_g2, D3w, D3b, out, BQ, 1024, 512);
}

// round 6
// speedup vs baseline: 1.6415x; 1.6415x over previous
#include <cuda_runtime.h>
#include <cuda_bf16.h>
#include <math.h>

// Problem constants (fixed by setup_inputs)
#define BQ    1024
#define DIM   1024
#define CDIM  128
#define NKEYS 100000
#define KNN   5
#define EPSW  1e-6f
#define CAP   49152
#define NB    2048
#define TAUB  128

// ---------------- scratch (device globals; no allocations allowed) ---------
__device__ __align__(16) __nv_bfloat16 g_qh[BQ * DIM],   g_ql[BQ * DIM];
__device__ __align__(16) __nv_bfloat16 g_W1h[DIM * 512], g_W1l[DIM * 512];
__device__ __align__(16) __nv_bfloat16 g_W2h[512 * 256], g_W2l[512 * 256];
__device__ __align__(16) __nv_bfloat16 g_W3h[256 * 128], g_W3l[256 * 128];
__device__ __align__(16) __nv_bfloat16 g_D1h[128 * 256], g_D1l[128 * 256];
__device__ __align__(16) __nv_bfloat16 g_D2h[256 * 512], g_D2l[256 * 512];
__device__ __align__(16) __nv_bfloat16 g_D3h[512 * 1024], g_D3l[512 * 1024];
__device__ __align__(16) __nv_bfloat16 g_h1h[BQ * 512], g_h1l[BQ * 512];
__device__ __align__(16) __nv_bfloat16 g_h2h[BQ * 256], g_h2l[BQ * 256];
__device__ __align__(16) __nv_bfloat16 g_wh[BQ * CDIM], g_wl[BQ * CDIM];
__device__ __align__(16) __nv_bfloat16 g_g1h[BQ * 256], g_g1l[BQ * 256];
__device__ __align__(16) __nv_bfloat16 g_g2h[BQ * 512], g_g2l[BQ * 512];

__device__ float g_cq[BQ * CDIM];
__device__ float g_qn[BQ];
__device__ int   g_Qmax_bits;
__device__ float g_kn[NKEYS];
__device__ float g_tau;
__device__ float g_invw;
__device__ float g_w;
__device__ int   g_hist[NB];
__device__ int   g_cursor[NB];
__device__ int   g_cand_count;
__device__ int   g_scand[CAP];
__device__ float g_skn[CAP];
__device__ float g_sblo[CAP];
__device__ float g_taupart[TAUB * KNN];

// ---------------- init ------------------------------------------------------
__global__ void init_kernel() {
    int t = blockIdx.x * blockDim.x + threadIdx.x;
    if (t == 0) { g_Qmax_bits = 0; g_cand_count = 0; }
    if (t < NB) g_hist[t] = 0;
}

// ---------------- batched fp32 -> bf16 hi/lo split --------------------------
struct SplitSeg { const float* src; __nv_bfloat16* h; __nv_bfloat16* l; };
struct SplitArgs { SplitSeg s[7]; int cum[8]; };

__global__ void split_batch_kernel(SplitArgs a) {
    int i = blockIdx.x * blockDim.x + threadIdx.x;   // float4 units
    if (i >= a.cum[7]) return;
    int sg = 0;
    while (i >= a.cum[sg + 1]) sg++;
    int j = i - a.cum[sg];
    float4 v = reinterpret_cast<const float4*>(a.s[sg].src)[j];
    float x[4] = {v.x, v.y, v.z, v.w};
    unsigned short h[4], l[4];
#pragma unroll
    for (int q = 0; q < 4; q++) {
        __nv_bfloat16 hb = __float2bfloat16(x[q]);
        __nv_bfloat16 lb = __float2bfloat16(x[q] - __bfloat162float(hb));
        h[q] = __bfloat16_as_ushort(hb);
        l[q] = __bfloat16_as_ushort(lb);
    }
    uint2 hp = {(unsigned)h[0] | ((unsigned)h[1] << 16),
                (unsigned)h[2] | ((unsigned)h[3] << 16)};
    uint2 lp = {(unsigned)l[0] | ((unsigned)l[1] << 16),
                (unsigned)l[2] | ((unsigned)l[3] << 16)};
    reinterpret_cast<uint2*>(a.s[sg].h)[j] = hp;
    reinterpret_cast<uint2*>(a.s[sg].l)[j] = lp;
}

// ============================================================================
// bf16 hi/lo tensor-core GEMM, pre-split inputs, cp.async double buffering.
// Tile 64x64, BK=32, 128 threads (4 warps; each warp a 32x32 tile:
// 2x m16 x 4x n8).  AhBh + AhBl + AlBh, fp32 accumulate.
// ============================================================================
#define GBM 64
#define GBN 64
#define GBK 32
#define ASTR 40
#define BSTR 72

__device__ __forceinline__ void mma_bf16(float c[4], const unsigned a[4],
                                         const unsigned b[2]) {
    asm volatile(
        "mma.sync.aligned.m16n8k16.row.col.f32.bf16.bf16.f32 "
        "{%0,%1,%2,%3}, {%4,%5,%6,%7}, {%8,%9}, {%0,%1,%2,%3};"
        : "+f"(c[0]), "+f"(c[1]), "+f"(c[2]), "+f"(c[3])
        : "r"(a[0]), "r"(a[1]), "r"(a[2]), "r"(a[3]), "r"(b[0]), "r"(b[1]));
}
__device__ __forceinline__ void ldmA(unsigned a[4], unsigned addr) {
    asm volatile("ldmatrix.sync.aligned.m8n8.x4.shared.b16 {%0,%1,%2,%3}, [%4];"
                 : "=r"(a[0]), "=r"(a[1]), "=r"(a[2]), "=r"(a[3]) : "r"(addr));
}
__device__ __forceinline__ void ldmB(unsigned b[2], unsigned addr) {
    asm volatile("ldmatrix.sync.aligned.m8n8.x2.trans.shared.b16 {%0,%1}, [%2];"
                 : "=r"(b[0]), "=r"(b[1]) : "r"(addr));
}
__device__ __forceinline__ void cpa16(unsigned dst, const void* src) {
    asm volatile("cp.async.cg.shared.global [%0], [%1], 16;"
                 :: "r"(dst), "l"(src));
}

template <int RELU, int WF32, int WBF>
__global__ __launch_bounds__(128, 4)
void bgemm(const __nv_bfloat16* __restrict__ Ah, const __nv_bfloat16* __restrict__ Al,
           const __nv_bfloat16* __restrict__ Bh, const __nv_bfloat16* __restrict__ Bl,
           const float* __restrict__ bias,
           float* __restrict__ Cf,
           __nv_bfloat16* __restrict__ Ch, __nv_bfloat16* __restrict__ Cl,
           int M, int N, int K) {
    __shared__ __align__(16) __nv_bfloat16 sA[2 * 2 * GBM * ASTR];
    __shared__ __align__(16) __nv_bfloat16 sB[2 * 2 * GBK * BSTR];

    const int tid  = threadIdx.x;
    const int lane = tid & 31;
    const int wid  = tid >> 5;
    const int wm   = wid & 1;       // 2 warps along M (32 rows each)
    const int wn   = wid >> 1;      // 2 warps along N (32 cols each)
    const int bm   = blockIdx.y * GBM;
    const int bn   = blockIdx.x * GBN;

    const unsigned saddrA = (unsigned)__cvta_generic_to_shared(sA);
    const unsigned saddrB = (unsigned)__cvta_generic_to_shared(sB);
    const unsigned aBufB  = GBM * ASTR * 2;
    const unsigned bBufB  = GBK * BSTR * 2;

    const int ar  = tid >> 1;           // A row 0..63
    const int ac0 = (tid & 1) << 4;     // A col 0 or 16
    const int br  = tid >> 3;           // B row 0..15 (+16)
    const int bc  = (tid & 7) << 3;     // B col 0..56

    const int a_r  = (lane & 7) + ((lane >> 3) & 1) * 8;
    const int a_k8 = (lane >> 4) * 8;
    const int b_r  = lane & 15;

    float acc[2][4][4];
#pragma unroll
    for (int mt = 0; mt < 2; mt++)
#pragma unroll
        for (int nt = 0; nt < 4; nt++)
#pragma unroll
            for (int i = 0; i < 4; i++) acc[mt][nt][i] = 0.f;

    const int ntk = K >> 5;

    auto stage = [&](int t, int buf) {
        const int k0 = t * GBK;
        size_t ga = (size_t)(bm + ar) * K + k0 + ac0;
        unsigned da = saddrA + (unsigned)(buf * 2) * aBufB + (ar * ASTR + ac0) * 2;
        cpa16(da,      Ah + ga);
        cpa16(da + 16, Ah + ga + 8);
        cpa16(da + aBufB,      Al + ga);
        cpa16(da + aBufB + 16, Al + ga + 8);
#pragma unroll
        for (int p = 0; p < 2; p++) {
            int rr = br + p * 16;
            size_t gb = (size_t)(k0 + rr) * N + bn + bc;
            unsigned db = saddrB + (unsigned)(buf * 2) * bBufB + (rr * BSTR + bc) * 2;
            cpa16(db,         Bh + gb);
            cpa16(db + bBufB, Bl + gb);
        }
        asm volatile("cp.async.commit_group;");
    };

    stage(0, 0);

    for (int t = 0; t < ntk; t++) {
        asm volatile("cp.async.wait_group 0;");
        __syncthreads();
        if (t + 1 < ntk) stage(t + 1, (t + 1) & 1);

        const int buf = t & 1;
        const unsigned base_ah = saddrA + (unsigned)(buf * 2) * aBufB;
        const unsigned base_al = base_ah + aBufB;
        const unsigned base_bh = saddrB + (unsigned)(buf * 2) * bBufB;
        const unsigned base_bl = base_bh + bBufB;

#pragma unroll
        for (int kk = 0; kk < GBK; kk += 16) {
            unsigned ah[2][4], al_[2][4];
#pragma unroll
            for (int mt = 0; mt < 2; mt++) {
                unsigned ro = ((wm * 32 + mt * 16 + a_r) * ASTR + kk + a_k8) * 2;
                ldmA(ah[mt],  base_ah + ro);
                ldmA(al_[mt], base_al + ro);
            }
#pragma unroll
            for (int nt = 0; nt < 4; nt++) {
                unsigned bh[2], bl_[2];
                unsigned bo = ((kk + b_r) * BSTR + wn * 32 + nt * 8) * 2;
                ldmB(bh,  base_bh + bo);
                ldmB(bl_, base_bl + bo);
#pragma unroll
                for (int mt = 0; mt < 2; mt++) {
                    mma_bf16(acc[mt][nt], ah[mt],  bh);
                    mma_bf16(acc[mt][nt], ah[mt],  bl_);
                    mma_bf16(acc[mt][nt], al_[mt], bh);
                }
            }
        }
        __syncthreads();
    }

    // epilogue
    const int g  = lane >> 2;
    const int tq = lane & 3;
#pragma unroll
    for (int mt = 0; mt < 2; mt++) {
#pragma unroll
        for (int nt = 0; nt < 4; nt++) {
            int row = bm + wm * 32 + mt * 16 + g;
            int col = bn + wn * 32 + nt * 8 + tq * 2;
            float bz0 = bias[col], bz1 = bias[col + 1];
            float v0 = acc[mt][nt][0] + bz0;
            float v1 = acc[mt][nt][1] + bz1;
            float v2 = acc[mt][nt][2] + bz0;
            float v3 = acc[mt][nt][3] + bz1;
            if (RELU) {
                v0 = fmaxf(v0, 0.f); v1 = fmaxf(v1, 0.f);
                v2 = fmaxf(v2, 0.f); v3 = fmaxf(v3, 0.f);
            }
            if (WF32) {
                float2 o0 = {v0, v1}, o1 = {v2, v3};
                *reinterpret_cast<float2*>(&Cf[(size_t)row * N + col]) = o0;
                *reinterpret_cast<float2*>(&Cf[(size_t)(row + 8) * N + col]) = o1;
            }
            if (WBF) {
                __nv_bfloat16 h0 = __float2bfloat16(v0);
                __nv_bfloat16 h1 = __float2bfloat16(v1);
                __nv_bfloat16 h2 = __float2bfloat16(v2);
                __nv_bfloat16 h3 = __float2bfloat16(v3);
                unsigned hp0 = (unsigned)__bfloat16_as_ushort(h0) |
                               ((unsigned)__bfloat16_as_ushort(h1) << 16);
                unsigned hp1 = (unsigned)__bfloat16_as_ushort(h2) |
                               ((unsigned)__bfloat16_as_ushort(h3) << 16);
                unsigned lp0 = (unsigned)__bfloat16_as_ushort(
                                   __float2bfloat16(v0 - __bfloat162float(h0))) |
                               ((unsigned)__bfloat16_as_ushort(
                                   __float2bfloat16(v1 - __bfloat162float(h1))) << 16);
                unsigned lp1 = (unsigned)__bfloat16_as_ushort(
                                   __float2bfloat16(v2 - __bfloat162float(h2))) |
                               ((unsigned)__bfloat16_as_ushort(
                                   __float2bfloat16(v3 - __bfloat162float(h3))) << 16);
                *reinterpret_cast<unsigned*>(&Ch[(size_t)row * N + col]) = hp0;
                *reinterpret_cast<unsigned*>(&Ch[(size_t)(row + 8) * N + col]) = hp1;
                *reinterpret_cast<unsigned*>(&Cl[(size_t)row * N + col]) = lp0;
                *reinterpret_cast<unsigned*>(&Cl[(size_t)(row + 8) * N + col]) = lp1;
            }
        }
    }
}

// ---------------- row squared-norms (rows of width 128) --------------------
__global__ void rownorm_kernel(const float* __restrict__ X,
                               float* __restrict__ out, int rows, int do_qmax) {
    int gw = (int)((blockIdx.x * (size_t)blockDim.x + threadIdx.x) >> 5);
    int lane = threadIdx.x & 31;
    if (gw >= rows) return;
    float4 v = reinterpret_cast<const float4*>(X + (size_t)gw * 128)[lane];
    float s = v.x * v.x + v.y * v.y + v.z * v.z + v.w * v.w;
#pragma unroll
    for (int o = 16; o; o >>= 1) s += __shfl_xor_sync(0xffffffffu, s, o);
    if (lane == 0) {
        out[gw] = s;
        if (do_qmax) atomicMax(&g_Qmax_bits, __float_as_int(s));
    }
}

// ---------------- tau: parallel 5-smallest of upper bounds -----------------
__global__ void tau_part_kernel() {
    __shared__ float sv[256 * KNN];
    const int tid = threadIdx.x;
    const float Q = sqrtf(__int_as_float(g_Qmax_bits));
    float t5[KNN] = {3.4e38f, 3.4e38f, 3.4e38f, 3.4e38f, 3.4e38f};
    for (int n = blockIdx.x * blockDim.x + tid; n < NKEYS;
         n += gridDim.x * blockDim.x) {
        float kn = g_kn[n];
        float u = kn + 2.f * Q * sqrtf(kn) + 1e-3f;
        if (u < t5[KNN - 1]) {
            int p = KNN - 1;
            while (p > 0 && t5[p - 1] > u) { t5[p] = t5[p - 1]; p--; }
            t5[p] = u;
        }
    }
#pragma unroll
    for (int i = 0; i < KNN; i++) sv[tid * KNN + i] = t5[i];
    __syncthreads();
    for (int stride = 128; stride >= 1; stride >>= 1) {
        if (tid < stride) {
            float a[KNN], b[KNN], m[KNN];
#pragma unroll
            for (int i = 0; i < KNN; i++) {
                a[i] = sv[tid * KNN + i];
                b[i] = sv[(tid + stride) * KNN + i];
            }
            int ia = 0, ib = 0;
#pragma unroll
            for (int i = 0; i < KNN; i++) m[i] = (a[ia] <= b[ib]) ? a[ia++] : b[ib++];
#pragma unroll
            for (int i = 0; i < KNN; i++) sv[tid * KNN + i] = m[i];
        }
        __syncthreads();
    }
    if (tid < KNN) g_taupart[blockIdx.x * KNN + tid] = sv[tid];
}

__global__ void tau_final_kernel() {
    __shared__ float sv[TAUB * KNN];
    const int tid = threadIdx.x;
#pragma unroll
    for (int i = 0; i < KNN; i++) sv[tid * KNN + i] = g_taupart[tid * KNN + i];
    __syncthreads();
    for (int stride = TAUB / 2; stride >= 1; stride >>= 1) {
        if (tid < stride) {
            float a[KNN], b[KNN], m[KNN];
#pragma unroll
            for (int i = 0; i < KNN; i++) {
                a[i] = sv[tid * KNN + i];
                b[i] = sv[(tid + stride) * KNN + i];
            }
            int ia = 0, ib = 0;
#pragma unroll
            for (int i = 0; i < KNN; i++) m[i] = (a[ia] <= b[ib]) ? a[ia++] : b[ib++];
#pragma unroll
            for (int i = 0; i < KNN; i++) sv[tid * KNN + i] = m[i];
        }
        __syncthreads();
    }
    if (tid == 0) {
        const float Q = sqrtf(__int_as_float(g_Qmax_bits));
        float tau = sv[KNN - 1] + 1e-2f;
        g_tau = tau;
        float r = Q + sqrtf(Q * Q + tau);
        float hi = r * r * 1.02f + 1.f;
        g_invw = (float)NB / hi;
        g_w = hi / (float)NB;
    }
}

// ---------------- candidate histogram / scan / scatter ---------------------
__global__ void cand_hist_kernel() {
    int n = blockIdx.x * blockDim.x + threadIdx.x;
    if (n >= NKEYS) return;
    float Q = sqrtf(__int_as_float(g_Qmax_bits));
    float kn = g_kn[n];
    float l = kn - 2.f * Q * sqrtf(kn) - 1e-3f;
    if (l <= g_tau) {
        int b = min(NB - 1, (int)(kn * g_invw));
        atomicAdd(&g_hist[b], 1);
    }
}

__global__ void scan_kernel() {
    __shared__ int s[NB];
    __shared__ int tmp[NB];
    const int tid = threadIdx.x;   // 1024
    for (int i = tid; i < NB; i += 1024) s[i] = g_hist[i];
    __syncthreads();
    for (int off = 1; off < NB; off <<= 1) {
        for (int i = tid; i < NB; i += 1024)
            tmp[i] = s[i] + (i >= off ? s[i - off] : 0);
        __syncthreads();
        for (int i = tid; i < NB; i += 1024) s[i] = tmp[i];
        __syncthreads();
    }
    for (int i = tid; i < NB; i += 1024)
        g_cursor[i] = (i == 0) ? 0 : s[i - 1];
    if (tid == 0) g_cand_count = s[NB - 1];
}

__global__ void scatter_kernel() {
    int n = blockIdx.x * blockDim.x + threadIdx.x;
    if (n >= NKEYS) return;
    float Q = sqrtf(__int_as_float(g_Qmax_bits));
    float kn = g_kn[n];
    float l = kn - 2.f * Q * sqrtf(kn) - 1e-3f;
    if (l <= g_tau) {
        int b = min(NB - 1, (int)(kn * g_invw));
        int pos = atomicAdd(&g_cursor[b], 1);
        if (pos < CAP) {
            g_scand[pos] = n;
            g_skn[pos]   = kn;
            g_sblo[pos]  = (float)b * g_w;
        }
    }
}

// ---------------- exact rescore + top-5 + weighted gather ------------------
__global__ __launch_bounds__(128, 8)
void rescore_kernel(const float* __restrict__ keys,
                    const float* __restrict__ values,
                    float* __restrict__ conf_out) {
    const int b = blockIdx.x;
    const int tid = threadIdx.x;
    __shared__ float sq[CDIM];
    __shared__ float dv[128];
    __shared__ int   di[128];
    __shared__ float rd[KNN];
    __shared__ int   ri[KNN];
    __shared__ float rv[128];
    __shared__ int   rvi[128];
    __shared__ int   rvj[128];
    __shared__ float sw[KNN];
    __shared__ int   s_stop;

    sq[tid] = g_cq[(size_t)b * CDIM + tid];
    if (tid < KNN) { rd[tid] = 3.4e38f; ri[tid] = 0x7fffffff; }
    if (tid == 0) s_stop = 0;
    int count = g_cand_count;
    if (count > CAP) count = CAP;
    const float qn = g_qn[b];
    const float qb = sqrtf(qn);
    __syncthreads();

    for (int c0 = 0; c0 < count; c0 += 128) {
        if (tid == 0 && c0 > 0) {
            float blo = g_sblo[c0];
            float lb = qn + blo - 2.f * qb * sqrtf(blo) - 1e-3f;
            if (lb > rd[KNN - 1]) s_stop = 1;
        }
        __syncthreads();
        if (s_stop) break;

        int len = min(128, count - c0);
        int j = c0 + tid;
        if (tid < len) {
            int n = g_scand[j];
            const float4* kr = reinterpret_cast<const float4*>(keys + (size_t)n * CDIM);
            const float4* sq4 = reinterpret_cast<const float4*>(sq);
            float a0 = 0.f, a1 = 0.f, a2 = 0.f, a3 = 0.f;
#pragma unroll
            for (int d = 0; d < CDIM / 4; d++) {
                float4 kv = __ldg(&kr[d]);
                float4 qv = sq4[d];
                a0 = fmaf(qv.x, kv.x, a0);
                a1 = fmaf(qv.y, kv.y, a1);
                a2 = fmaf(qv.z, kv.z, a2);
                a3 = fmaf(qv.w, kv.w, a3);
            }
            float dot = (a0 + a1) + (a2 + a3);
            dv[tid] = qn + g_skn[j] - 2.f * dot;
            di[tid] = n;
        } else {
            dv[tid] = 3.4e38f;
            di[tid] = 0x7fffffff;
        }
        __syncthreads();

        for (int r = 0; r < KNN; r++) {
            rv[tid] = dv[tid]; rvi[tid] = di[tid]; rvj[tid] = tid;
            __syncthreads();
#pragma unroll
            for (int s = 64; s >= 1; s >>= 1) {
                if (tid < s) {
                    if (rv[tid + s] < rv[tid] ||
                        (rv[tid + s] == rv[tid] && rvi[tid + s] < rvi[tid])) {
                        rv[tid] = rv[tid + s];
                        rvi[tid] = rvi[tid + s];
                        rvj[tid] = rvj[tid + s];
                    }
                }
                __syncthreads();
            }
            if (tid == 0) {
                float v = rv[0]; int n = rvi[0];
                if (v < rd[KNN - 1] || (v == rd[KNN - 1] && n < ri[KNN - 1])) {
                    int p = KNN - 1;
                    while (p > 0 && (rd[p - 1] > v ||
                                     (rd[p - 1] == v && ri[p - 1] > n))) {
                        rd[p] = rd[p - 1]; ri[p] = ri[p - 1]; p--;
                    }
                    rd[p] = v; ri[p] = n;
                }
                dv[rvj[0]] = 3.4e38f;
            }
            __syncthreads();
        }
    }

    if (tid == 0) {
        float w[KNN], ws = 0.f;
#pragma unroll
        for (int j2 = 0; j2 < KNN; j2++) { w[j2] = 1.f / (rd[j2] + EPSW); ws += w[j2]; }
#pragma unroll
        for (int j2 = 0; j2 < KNN; j2++) sw[j2] = w[j2] / ws;
        conf_out[b] = 1.f / (rd[0] + EPSW);
    }
    __syncthreads();

    float acc = 0.f;
#pragma unroll
    for (int j2 = 0; j2 < KNN; j2++)
        acc += sw[j2] * values[(size_t)ri[j2] * CDIM + tid];
    __nv_bfloat16 hb = __float2bfloat16(acc);
    g_wh[(size_t)b * CDIM + tid] = hb;
    g_wl[(size_t)b * CDIM + tid] = __float2bfloat16(acc - __bfloat162float(hb));
}

// ---------------- launch ----------------------------------------------------
extern "C" void kernel_launch(void* const* d_in, const int* in_sizes, int n_in,
                              void* d_out, int out_size) {
    const float* query = (const float*)d_in[0];
    const float* W1    = (const float*)d_in[1];
    const float* b1    = (const float*)d_in[2];
    const float* W2    = (const float*)d_in[3];
    const float* b2    = (const float*)d_in[4];
    const float* W3    = (const float*)d_in[5];
    const float* b3    = (const float*)d_in[6];
    const float* keys  = (const float*)d_in[7];
    const float* values= (const float*)d_in[8];
    const float* D1w   = (const float*)d_in[9];
    const float* D1b   = (const float*)d_in[10];
    const float* D2w   = (const float*)d_in[11];
    const float* D2b   = (const float*)d_in[12];
    const float* D3w   = (const float*)d_in[13];
    const float* D3b   = (const float*)d_in[14];

    float* out  = (float*)d_out;
    float* conf = out + (size_t)BQ * DIM;

    void *qh, *ql, *W1h, *W1l, *W2h, *W2l, *W3h, *W3l;
    void *D1h, *D1l, *D2h, *D2l, *D3h, *D3l;
    void *h1h, *h1l, *h2h, *h2l, *wh, *wl, *g1h, *g1l, *g2h, *g2l;
    void *cq, *qn, *kn;
    cudaGetSymbolAddress(&qh, g_qh);   cudaGetSymbolAddress(&ql, g_ql);
    cudaGetSymbolAddress(&W1h, g_W1h); cudaGetSymbolAddress(&W1l, g_W1l);
    cudaGetSymbolAddress(&W2h, g_W2h); cudaGetSymbolAddress(&W2l, g_W2l);
    cudaGetSymbolAddress(&W3h, g_W3h); cudaGetSymbolAddress(&W3l, g_W3l);
    cudaGetSymbolAddress(&D1h, g_D1h); cudaGetSymbolAddress(&D1l, g_D1l);
    cudaGetSymbolAddress(&D2h, g_D2h); cudaGetSymbolAddress(&D2l, g_D2l);
    cudaGetSymbolAddress(&D3h, g_D3h); cudaGetSymbolAddress(&D3l, g_D3l);
    cudaGetSymbolAddress(&h1h, g_h1h); cudaGetSymbolAddress(&h1l, g_h1l);
    cudaGetSymbolAddress(&h2h, g_h2h); cudaGetSymbolAddress(&h2l, g_h2l);
    cudaGetSymbolAddress(&wh, g_wh);   cudaGetSymbolAddress(&wl, g_wl);
    cudaGetSymbolAddress(&g1h, g_g1h); cudaGetSymbolAddress(&g1l, g_g1l);
    cudaGetSymbolAddress(&g2h, g_g2h); cudaGetSymbolAddress(&g2l, g_g2l);
    cudaGetSymbolAddress(&cq, g_cq);
    cudaGetSymbolAddress(&qn, g_qn);
    cudaGetSymbolAddress(&kn, g_kn);

    init_kernel<<<NB / 256, 256>>>();

    // batched split: query + 6 weight matrices
    SplitArgs sa;
    int sizes4[7] = {BQ * DIM / 4, DIM * 512 / 4, 512 * 256 / 4, 256 * 128 / 4,
                     128 * 256 / 4, 256 * 512 / 4, 512 * 1024 / 4};
    const float* srcs[7] = {query, W1, W2, W3, D1w, D2w, D3w};
    void* hs[7] = {qh, W1h, W2h, W3h, D1h, D2h, D3h};
    void* ls[7] = {ql, W1l, W2l, W3l, D1l, D2l, D3l};
    sa.cum[0] = 0;
    for (int i = 0; i < 7; i++) {
        sa.s[i].src = srcs[i];
        sa.s[i].h = (__nv_bfloat16*)hs[i];
        sa.s[i].l = (__nv_bfloat16*)ls[i];
        sa.cum[i + 1] = sa.cum[i] + sizes4[i];
    }
    split_batch_kernel<<<(sa.cum[7] + 255) / 256, 256>>>(sa);

    // key norms (independent)
    rownorm_kernel<<<(NKEYS * 32 + 255) / 256, 256>>>(keys, (float*)kn, NKEYS, 0);

    // Encode MLP
    bgemm<1, 0, 1><<<dim3(512 / GBN, BQ / GBM), 128>>>(
        (__nv_bfloat16*)qh, (__nv_bfloat16*)ql, (__nv_bfloat16*)W1h, (__nv_bfloat16*)W1l,
        b1, nullptr, (__nv_bfloat16*)h1h, (__nv_bfloat16*)h1l, BQ, 512, 1024);
    bgemm<1, 0, 1><<<dim3(256 / GBN, BQ / GBM), 128>>>(
        (__nv_bfloat16*)h1h, (__nv_bfloat16*)h1l, (__nv_bfloat16*)W2h, (__nv_bfloat16*)W2l,
        b2, nullptr, (__nv_bfloat16*)h2h, (__nv_bfloat16*)h2l, BQ, 256, 512);
    bgemm<0, 1, 0><<<dim3(128 / GBN, BQ / GBM), 128>>>(
        (__nv_bfloat16*)h2h, (__nv_bfloat16*)h2l, (__nv_bfloat16*)W3h, (__nv_bfloat16*)W3l,
        b3, (float*)cq, nullptr, nullptr, BQ, 128, 256);

    // query norms + Qmax
    rownorm_kernel<<<(BQ * 32 + 255) / 256, 256>>>((float*)cq, (float*)qn, BQ, 1);

    // candidate filter -> bucket-sorted list
    tau_part_kernel<<<TAUB, 256>>>();
    tau_final_kernel<<<1, TAUB>>>();
    cand_hist_kernel<<<(NKEYS + 255) / 256, 256>>>();
    scan_kernel<<<1, 1024>>>();
    scatter_kernel<<<(NKEYS + 255) / 256, 256>>>();

    // exact rescore + top-5 + gather (emits weighted as bf16 hi/lo)
    rescore_kernel<<<BQ, 128>>>(keys, values, conf);

    // Decode MLP
    bgemm<1, 0, 1><<<dim3(256 / GBN, BQ / GBM), 128>>>(
        (__nv_bfloat16*)wh, (__nv_bfloat16*)wl, (__nv_bfloat16*)D1h, (__nv_bfloat16*)D1l,
        D1b, nullptr, (__nv_bfloat16*)g1h, (__nv_bfloat16*)g1l, BQ, 256, 128);
    bgemm<1, 0, 1><<<dim3(512 / GBN, BQ / GBM), 128>>>(
        (__nv_bfloat16*)g1h, (__nv_bfloat16*)g1l, (__nv_bfloat16*)D2h, (__nv_bfloat16*)D2l,
        D2b, nullptr, (__nv_bfloat16*)g2h, (__nv_bfloat16*)g2l, BQ, 512, 256);
    bgemm<0, 1, 0><<<dim3(1024 / GBN, BQ / GBM), 128>>>(
        (__nv_bfloat16*)g2h, (__nv_bfloat16*)g2l, (__nv_bfloat16*)D3h, (__nv_bfloat16*)D3l,
        D3b, out, nullptr, nullptr, BQ, 1024, 512);
}